// round 1
// baseline (speedup 1.0000x reference)
#include <cuda_runtime.h>
#include <math.h>

// ---------------------------------------------------------------------------
// DiffusionLoss (AF3-style): Kabsch-align GT onto pred, weighted coord loss +
// pairwise distance ("bond") loss, scaled per-batch by (ht^2+sd^2)/(ht+sd)^2.
// Inputs (metadata order): xpred [B,N,3] f32, xGT [B,N,3] f32, ht [B] f32,
//                          w [B,N] f32.  Output: [B] f32.
// ---------------------------------------------------------------------------

#define MAXB 16

__device__ double g_W[MAXB];     // per-batch sum of weights
__device__ double g_num1[MAXB];  // per-batch aligned-coordinate loss numerator
__device__ double g_bond;        // global bond numerator (sum over all b,i,j)

__device__ __forceinline__ float fsqrt_approx(float x) {
    float r;
    asm("sqrt.approx.f32 %0, %1;" : "=f"(r) : "f"(x));
    return r;
}

// ---------------------------------------------------------------------------
// Kernel 1: per-batch stats, 3x3 SVD (Kabsch rotation), alignment loss.
// One block per batch, 256 threads.
// ---------------------------------------------------------------------------
__global__ void stats_align_kernel(const float* __restrict__ pred,
                                   const float* __restrict__ gt,
                                   const float* __restrict__ w,
                                   int N)
{
    const int b = blockIdx.x;
    const int t = threadIdx.x;
    const int nthr = blockDim.x;
    const float* pb = pred + (size_t)b * N * 3;
    const float* gb = gt   + (size_t)b * N * 3;
    const float* wb = w    + (size_t)b * N;

    if (b == 0 && t == 0) g_bond = 0.0;   // reset for the pair kernel (runs after)

    // acc layout: [0]=W, [1..3]=sum w*p, [4..6]=sum w*g, [7..15]=sum w*p_i*g_j
    double acc[16];
#pragma unroll
    for (int i = 0; i < 16; i++) acc[i] = 0.0;

    for (int n = t; n < N; n += nthr) {
        double wn = (double)wb[n];
        double px = pb[3*n], py = pb[3*n+1], pz = pb[3*n+2];
        double gx = gb[3*n], gy = gb[3*n+1], gz = gb[3*n+2];
        acc[0]  += wn;
        acc[1]  += wn*px;  acc[2]  += wn*py;  acc[3]  += wn*pz;
        acc[4]  += wn*gx;  acc[5]  += wn*gy;  acc[6]  += wn*gz;
        acc[7]  += wn*px*gx; acc[8]  += wn*px*gy; acc[9]  += wn*px*gz;
        acc[10] += wn*py*gx; acc[11] += wn*py*gy; acc[12] += wn*py*gz;
        acc[13] += wn*pz*gx; acc[14] += wn*pz*gy; acc[15] += wn*pz*gz;
    }

    const unsigned mask = 0xffffffffu;
#pragma unroll
    for (int i = 0; i < 16; i++)
        for (int o = 16; o > 0; o >>= 1)
            acc[i] += __shfl_down_sync(mask, acc[i], o);

    __shared__ double sred[8][16];
    __shared__ float  sPar[15];   // R[9], mu[3] (gt mean), muGT[3] (pred mean)
    int warp = t >> 5, lane = t & 31;
    int nwarps = nthr >> 5;
    if (lane == 0)
#pragma unroll
        for (int i = 0; i < 16; i++) sred[warp][i] = acc[i];
    __syncthreads();

    if (t == 0) {
        double v[16];
        for (int i = 0; i < 16; i++) {
            double s = 0.0;
            for (int wi = 0; wi < nwarps; wi++) s += sred[wi][i];
            v[i] = s;
        }
        double W = v[0];
        // Note arg swap in reference: mu = GT weighted mean, muGT = pred mean.
        double muGT[3] = { v[1]/W, v[2]/W, v[3]/W };
        double mu[3]   = { v[4]/W, v[5]/W, v[6]/W };
        // M_ij = sum w * (pred_i - muGT_i)(gt_j - mu_j) = Spg_ij - Sp_i*Sg_j/W
        double A[3][3];
        for (int i = 0; i < 3; i++)
            for (int j = 0; j < 3; j++)
                A[i][j] = v[7 + i*3 + j] - v[1+i]*v[4+j]/W;

        double detA = A[0][0]*(A[1][1]*A[2][2]-A[1][2]*A[2][1])
                    - A[0][1]*(A[1][0]*A[2][2]-A[1][2]*A[2][0])
                    + A[0][2]*(A[1][0]*A[2][1]-A[1][1]*A[2][0]);

        // C = A^T A, Jacobi eigendecomposition C = V diag(eig) V^T
        double C[3][3];
        for (int i = 0; i < 3; i++)
            for (int j = 0; j < 3; j++) {
                double s = 0.0;
                for (int k = 0; k < 3; k++) s += A[k][i]*A[k][j];
                C[i][j] = s;
            }
        double V[3][3] = {{1,0,0},{0,1,0},{0,0,1}};
        for (int sweep = 0; sweep < 30; sweep++) {
            double off = C[0][1]*C[0][1] + C[0][2]*C[0][2] + C[1][2]*C[1][2];
            if (off < 1e-26) break;
            for (int p = 0; p < 3; p++)
                for (int q = p+1; q < 3; q++) {
                    double apq = C[p][q];
                    if (fabs(apq) < 1e-300) continue;
                    double theta = (C[q][q] - C[p][p]) / (2.0 * apq);
                    double tt = (theta >= 0.0 ? 1.0 : -1.0) /
                                (fabs(theta) + sqrt(theta*theta + 1.0));
                    double c = 1.0 / sqrt(tt*tt + 1.0), s = tt * c;
                    for (int k = 0; k < 3; k++) {
                        double a = C[k][p], bb = C[k][q];
                        C[k][p] = c*a - s*bb;  C[k][q] = s*a + c*bb;
                    }
                    for (int k = 0; k < 3; k++) {
                        double a = C[p][k], bb = C[q][k];
                        C[p][k] = c*a - s*bb;  C[q][k] = s*a + c*bb;
                    }
                    for (int k = 0; k < 3; k++) {
                        double a = V[k][p], bb = V[k][q];
                        V[k][p] = c*a - s*bb;  V[k][q] = s*a + c*bb;
                    }
                }
        }
        double eig[3] = { C[0][0], C[1][1], C[2][2] };
        int idx[3] = {0, 1, 2};
        for (int i = 0; i < 2; i++)
            for (int j = i+1; j < 3; j++)
                if (eig[idx[j]] > eig[idx[i]]) { int tmp = idx[i]; idx[i] = idx[j]; idx[j] = tmp; }

        double dinv[3];
        for (int i = 0; i < 3; i++) {
            double e = eig[idx[i]];
            double si = sqrt(e > 0.0 ? e : 0.0);
            dinv[i] = (si > 1e-12) ? 1.0/si : 0.0;
        }
        if (detA < 0.0) dinv[2] = -dinv[2];   // flip smallest singular direction

        // R = U * diag(1,1,sgn) * V^T = A * Vs * diag(dinv) * Vs^T
        double T[3][3];
        for (int i = 0; i < 3; i++)
            for (int j = 0; j < 3; j++) {
                double s = 0.0;
                for (int k = 0; k < 3; k++) s += A[i][k] * V[k][idx[j]];
                T[i][j] = s * dinv[j];
            }
        for (int i = 0; i < 3; i++)
            for (int j = 0; j < 3; j++) {
                double s = 0.0;
                for (int k = 0; k < 3; k++) s += T[i][k] * V[j][idx[k]];
                sPar[i*3 + j] = (float)s;
            }
        sPar[9]  = (float)mu[0];   sPar[10] = (float)mu[1];   sPar[11] = (float)mu[2];
        sPar[12] = (float)muGT[0]; sPar[13] = (float)muGT[1]; sPar[14] = (float)muGT[2];
        g_W[b] = W;
    }
    __syncthreads();

    // Alignment loss: sum_n w_n * || p_n - (R (g_n - mu) + muGT) ||
    float R00 = sPar[0], R01 = sPar[1], R02 = sPar[2];
    float R10 = sPar[3], R11 = sPar[4], R12 = sPar[5];
    float R20 = sPar[6], R21 = sPar[7], R22 = sPar[8];
    float mux = sPar[9], muy = sPar[10], muz = sPar[11];
    float mgx = sPar[12], mgy = sPar[13], mgz = sPar[14];

    double part = 0.0;
    for (int n = t; n < N; n += nthr) {
        float wn = wb[n];
        float gx = gb[3*n]   - mux;
        float gy = gb[3*n+1] - muy;
        float gz = gb[3*n+2] - muz;
        float ax = R00*gx + R01*gy + R02*gz + mgx;
        float ay = R10*gx + R11*gy + R12*gz + mgy;
        float az = R20*gx + R21*gy + R22*gz + mgz;
        float dx = pb[3*n]   - ax;
        float dy = pb[3*n+1] - ay;
        float dz = pb[3*n+2] - az;
        float sq = dx*dx + dy*dy + dz*dz;
        part += (double)(wn * fsqrt_approx(sq));
    }
    for (int o = 16; o > 0; o >>= 1)
        part += __shfl_down_sync(mask, part, o);
    __shared__ double sred2[8];
    if (lane == 0) sred2[warp] = part;
    __syncthreads();
    if (t == 0) {
        double s = 0.0;
        for (int wi = 0; wi < nwarps; wi++) s += sred2[wi];
        g_num1[b] = s;
    }
}

// ---------------------------------------------------------------------------
// Kernel 2: pairwise bond term. Each block does a (TI x TJ) tile of one batch.
// (d_pred - d_gt)^2 = dp2 + dg2 - 2*sqrt(dp2*dg2)  -> one MUFU per pair.
// ---------------------------------------------------------------------------
#define PAIR_THREADS 128
#define TI 256   // rows per block (2 per thread)
#define TJ 256   // cols per block (shared tile)

__global__ void __launch_bounds__(PAIR_THREADS)
pair_kernel(const float* __restrict__ pred,
            const float* __restrict__ gt,
            const float* __restrict__ w,
            int N, int tilesI, int tilesJ)
{
    int blk = blockIdx.x;
    int tilesPerB = tilesI * tilesJ;
    int b   = blk / tilesPerB;
    int rem = blk % tilesPerB;
    int ti = rem / tilesJ;
    int tj = rem % tilesJ;

    const float* pb = pred + (size_t)b * N * 3;
    const float* gb = gt   + (size_t)b * N * 3;
    const float* wb = w    + (size_t)b * N;

    __shared__ float4 spj[TJ];   // pred_j (x,y,z) + w_j
    __shared__ float4 sgj[TJ];   // gt_j   (x,y,z)

    const int t = threadIdx.x;
    for (int k = t; k < TJ; k += PAIR_THREADS) {
        int j = tj * TJ + k;
        float4 p4 = make_float4(0.f, 0.f, 0.f, 0.f);
        float4 g4 = make_float4(0.f, 0.f, 0.f, 0.f);
        if (j < N) {
            p4.x = pb[3*j]; p4.y = pb[3*j+1]; p4.z = pb[3*j+2]; p4.w = wb[j];
            g4.x = gb[3*j]; g4.y = gb[3*j+1]; g4.z = gb[3*j+2];
        }
        spj[k] = p4;
        sgj[k] = g4;
    }

    // two i-rows per thread
    int i0 = ti * TI + t;
    int i1 = i0 + PAIR_THREADS;
    float p0x=0.f,p0y=0.f,p0z=0.f,g0x=0.f,g0y=0.f,g0z=0.f,w0=0.f;
    float p1x=0.f,p1y=0.f,p1z=0.f,g1x=0.f,g1y=0.f,g1z=0.f,w1=0.f;
    if (i0 < N) {
        p0x = pb[3*i0]; p0y = pb[3*i0+1]; p0z = pb[3*i0+2]; w0 = wb[i0];
        g0x = gb[3*i0]; g0y = gb[3*i0+1]; g0z = gb[3*i0+2];
    }
    if (i1 < N) {
        p1x = pb[3*i1]; p1y = pb[3*i1+1]; p1z = pb[3*i1+2]; w1 = wb[i1];
        g1x = gb[3*i1]; g1y = gb[3*i1+1]; g1z = gb[3*i1+2];
    }
    __syncthreads();

    float acc0 = 0.f, acc1 = 0.f;
#pragma unroll 4
    for (int k = 0; k < TJ; k++) {
        float4 pj = spj[k];
        float4 gj = sgj[k];
        // row i0
        {
            float dx = p0x - pj.x, dy = p0y - pj.y, dz = p0z - pj.z;
            float dp2 = dx*dx + dy*dy + dz*dz;
            float ex = g0x - gj.x, ey = g0y - gj.y, ez = g0z - gj.z;
            float dg2 = ex*ex + ey*ey + ez*ez;
            float s = fsqrt_approx(dp2 * dg2);
            float term = dp2 + dg2 - 2.f * s;
            acc0 = fmaf(w0 * pj.w, term, acc0);
        }
        // row i1
        {
            float dx = p1x - pj.x, dy = p1y - pj.y, dz = p1z - pj.z;
            float dp2 = dx*dx + dy*dy + dz*dz;
            float ex = g1x - gj.x, ey = g1y - gj.y, ez = g1z - gj.z;
            float dg2 = ex*ex + ey*ey + ez*ez;
            float s = fsqrt_approx(dp2 * dg2);
            float term = dp2 + dg2 - 2.f * s;
            acc1 = fmaf(w1 * pj.w, term, acc1);
        }
    }

    double tot = (double)acc0 + (double)acc1;
    const unsigned mask = 0xffffffffu;
    for (int o = 16; o > 0; o >>= 1)
        tot += __shfl_down_sync(mask, tot, o);
    __shared__ double sredp[PAIR_THREADS/32];
    int warp = t >> 5, lane = t & 31;
    if (lane == 0) sredp[warp] = tot;
    __syncthreads();
    if (t == 0) {
        double s = 0.0;
        for (int wi = 0; wi < PAIR_THREADS/32; wi++) s += sredp[wi];
        atomicAdd(&g_bond, s);
    }
}

// ---------------------------------------------------------------------------
// Kernel 3: final scalar combination + per-batch ht scaling.
// ---------------------------------------------------------------------------
__global__ void final_kernel(const float* __restrict__ ht,
                             float* __restrict__ out, int B)
{
    if (threadIdx.x == 0 && blockIdx.x == 0) {
        double sw = 0.0, sw2 = 0.0, sn = 0.0;
        for (int b = 0; b < B; b++) {
            double W = g_W[b];
            sw += W; sw2 += W * W; sn += g_num1[b];
        }
        double loss = sn / sw + g_bond / sw2;   // ALPHA_BOND = 1
        for (int b = 0; b < B; b++) {
            double h = (double)ht[b];
            out[b] = (float)(((h*h + 256.0) / ((h + 16.0) * (h + 16.0))) * loss);
        }
    }
}

extern "C" void kernel_launch(void* const* d_in, const int* in_sizes, int n_in,
                              void* d_out, int out_size)
{
    const float* pred = (const float*)d_in[0];
    const float* gt   = (const float*)d_in[1];
    const float* ht   = (const float*)d_in[2];
    const float* w    = (const float*)d_in[3];
    int B = in_sizes[2];
    int N = in_sizes[3] / B;

    stats_align_kernel<<<B, 256>>>(pred, gt, w, N);

    int tilesI = (N + TI - 1) / TI;
    int tilesJ = (N + TJ - 1) / TJ;
    pair_kernel<<<B * tilesI * tilesJ, PAIR_THREADS>>>(pred, gt, w, N, tilesI, tilesJ);

    final_kernel<<<1, 32>>>(ht, (float*)d_out, B);
}

// round 2
// speedup vs baseline: 3.1090x; 3.1090x over previous
#include <cuda_runtime.h>
#include <math.h>

// ---------------------------------------------------------------------------
// DiffusionLoss (AF3-style): Kabsch-align GT onto pred, weighted coord loss +
// pairwise distance ("bond") loss, scaled per-batch by (ht^2+sd^2)/(ht+sd)^2.
// Inputs: xpred [B,N,3] f32, xGT [B,N,3] f32, ht [B] f32, w [B,N] f32.
// Output: [B] f32.
// ---------------------------------------------------------------------------

#define MAXB 16

__device__ double g_W[MAXB];     // per-batch sum of weights
__device__ double g_num1[MAXB];  // per-batch aligned-coordinate loss numerator
__device__ double g_bond;        // global bond numerator

__device__ __forceinline__ float fsqrt_approx(float x) {
    float r;
    asm("sqrt.approx.f32 %0, %1;" : "=f"(r) : "f"(x));
    return r;
}

// ---------------------------------------------------------------------------
// Kernel 1: per-batch stats, 3x3 Kabsch solve (float Jacobi), alignment loss.
// One block per batch, 256 threads.
// ---------------------------------------------------------------------------
__global__ void stats_align_kernel(const float* __restrict__ pred,
                                   const float* __restrict__ gt,
                                   const float* __restrict__ w,
                                   int N)
{
    const int b = blockIdx.x;
    const int t = threadIdx.x;
    const int nthr = blockDim.x;
    const float* pb = pred + (size_t)b * N * 3;
    const float* gb = gt   + (size_t)b * N * 3;
    const float* wb = w    + (size_t)b * N;

    if (b == 0 && t == 0) g_bond = 0.0;   // reset for pair kernel (runs after)

    // acc: [0]=W, [1..3]=sum w*p, [4..6]=sum w*g, [7..15]=sum w*p_i*g_j
    float acc[16];
#pragma unroll
    for (int i = 0; i < 16; i++) acc[i] = 0.f;

    for (int n = t; n < N; n += nthr) {
        float wn = wb[n];
        float px = pb[3*n], py = pb[3*n+1], pz = pb[3*n+2];
        float gx = gb[3*n], gy = gb[3*n+1], gz = gb[3*n+2];
        float wpx = wn*px, wpy = wn*py, wpz = wn*pz;
        acc[0]  += wn;
        acc[1]  += wpx;  acc[2]  += wpy;  acc[3]  += wpz;
        acc[4]  += wn*gx; acc[5]  += wn*gy; acc[6]  += wn*gz;
        acc[7]  += wpx*gx; acc[8]  += wpx*gy; acc[9]  += wpx*gz;
        acc[10] += wpy*gx; acc[11] += wpy*gy; acc[12] += wpy*gz;
        acc[13] += wpz*gx; acc[14] += wpz*gy; acc[15] += wpz*gz;
    }

    const unsigned mask = 0xffffffffu;
    double accd[16];
#pragma unroll
    for (int i = 0; i < 16; i++) accd[i] = (double)acc[i];
#pragma unroll
    for (int i = 0; i < 16; i++)
        for (int o = 16; o > 0; o >>= 1)
            accd[i] += __shfl_down_sync(mask, accd[i], o);

    __shared__ double sred[8][16];
    __shared__ float  sPar[15];   // R[9], mu(gt mean)[3], muGT(pred mean)[3]
    int warp = t >> 5, lane = t & 31;
    int nwarps = nthr >> 5;
    if (lane == 0)
#pragma unroll
        for (int i = 0; i < 16; i++) sred[warp][i] = accd[i];
    __syncthreads();

    if (t == 0) {
        double v[16];
        for (int i = 0; i < 16; i++) {
            double s = 0.0;
            for (int wi = 0; wi < nwarps; wi++) s += sred[wi][i];
            v[i] = s;
        }
        double W = v[0];
        double invW = 1.0 / W;                 // the ONLY fp64 div/sqrt op
        // mu = GT weighted mean, muGT = pred mean (arg-swap in reference)
        float muGT[3] = { (float)(v[1]*invW), (float)(v[2]*invW), (float)(v[3]*invW) };
        float mu[3]   = { (float)(v[4]*invW), (float)(v[5]*invW), (float)(v[6]*invW) };

        // A_ij = sum w (pred_i - p̄_i)(gt_j - ḡ_j)  (float from here on)
        float A[3][3];
        for (int i = 0; i < 3; i++)
            for (int j = 0; j < 3; j++)
                A[i][j] = (float)(v[7 + i*3 + j] - v[1+i]*v[4+j]*invW);

        float detA = A[0][0]*(A[1][1]*A[2][2]-A[1][2]*A[2][1])
                   - A[0][1]*(A[1][0]*A[2][2]-A[1][2]*A[2][0])
                   + A[0][2]*(A[1][0]*A[2][1]-A[1][1]*A[2][0]);

        // C = A^T A; Jacobi eigendecomposition C = V diag(eig) V^T (float)
        float C[3][3];
        for (int i = 0; i < 3; i++)
            for (int j = 0; j < 3; j++) {
                float s = 0.f;
                for (int k = 0; k < 3; k++) s += A[k][i]*A[k][j];
                C[i][j] = s;
            }
        float V[3][3] = {{1,0,0},{0,1,0},{0,0,1}};
#pragma unroll
        for (int sweep = 0; sweep < 6; sweep++) {
#pragma unroll
            for (int p = 0; p < 3; p++)
#pragma unroll
                for (int q = p+1; q < 3; q++) {
                    float apq = C[p][q];
                    if (apq == 0.f) continue;
                    float theta = __fdividef(C[q][q] - C[p][p], 2.f * apq);
                    float tt = (theta >= 0.f ? 1.f : -1.f) *
                               __fdividef(1.f, fabsf(theta) + sqrtf(theta*theta + 1.f));
                    float c = rsqrtf(tt*tt + 1.f), s = tt * c;
                    for (int k = 0; k < 3; k++) {
                        float a = C[k][p], bb = C[k][q];
                        C[k][p] = c*a - s*bb;  C[k][q] = s*a + c*bb;
                    }
                    for (int k = 0; k < 3; k++) {
                        float a = C[p][k], bb = C[q][k];
                        C[p][k] = c*a - s*bb;  C[q][k] = s*a + c*bb;
                    }
                    for (int k = 0; k < 3; k++) {
                        float a = V[k][p], bb = V[k][q];
                        V[k][p] = c*a - s*bb;  V[k][q] = s*a + c*bb;
                    }
                }
        }
        float eig[3] = { C[0][0], C[1][1], C[2][2] };
        int idx[3] = {0, 1, 2};
        for (int i = 0; i < 2; i++)
            for (int j = i+1; j < 3; j++)
                if (eig[idx[j]] > eig[idx[i]]) { int tmp = idx[i]; idx[i] = idx[j]; idx[j] = tmp; }

        float emax = fmaxf(eig[idx[0]], 0.f);
        float dinv[3];
        for (int i = 0; i < 3; i++) {
            float e = fmaxf(eig[idx[i]], 0.f);
            dinv[i] = (e > 1e-12f * emax && e > 0.f) ? rsqrtf(e) : 0.f;
        }
        if (detA < 0.f) dinv[2] = -dinv[2];   // flip smallest singular direction

        // R = A * Vs * diag(dinv) * Vs^T
        float T[3][3];
        for (int i = 0; i < 3; i++)
            for (int j = 0; j < 3; j++) {
                float s = 0.f;
                for (int k = 0; k < 3; k++) s += A[i][k] * V[k][idx[j]];
                T[i][j] = s * dinv[j];
            }
        for (int i = 0; i < 3; i++)
            for (int j = 0; j < 3; j++) {
                float s = 0.f;
                for (int k = 0; k < 3; k++) s += T[i][k] * V[j][idx[k]];
                sPar[i*3 + j] = s;
            }
        sPar[9]  = mu[0];   sPar[10] = mu[1];   sPar[11] = mu[2];
        sPar[12] = muGT[0]; sPar[13] = muGT[1]; sPar[14] = muGT[2];
        g_W[b] = W;
    }
    __syncthreads();

    // Alignment loss: sum_n w_n * || p_n - (R (g_n - mu) + muGT) ||
    float R00 = sPar[0], R01 = sPar[1], R02 = sPar[2];
    float R10 = sPar[3], R11 = sPar[4], R12 = sPar[5];
    float R20 = sPar[6], R21 = sPar[7], R22 = sPar[8];
    float mux = sPar[9], muy = sPar[10], muz = sPar[11];
    float mgx = sPar[12], mgy = sPar[13], mgz = sPar[14];

    float partf = 0.f;
    for (int n = t; n < N; n += nthr) {
        float wn = wb[n];
        float gx = gb[3*n]   - mux;
        float gy = gb[3*n+1] - muy;
        float gz = gb[3*n+2] - muz;
        float ax = R00*gx + R01*gy + R02*gz + mgx;
        float ay = R10*gx + R11*gy + R12*gz + mgy;
        float az = R20*gx + R21*gy + R22*gz + mgz;
        float dx = pb[3*n]   - ax;
        float dy = pb[3*n+1] - ay;
        float dz = pb[3*n+2] - az;
        float sq = dx*dx + dy*dy + dz*dz;
        partf += wn * fsqrt_approx(sq);
    }
    double part = (double)partf;
    for (int o = 16; o > 0; o >>= 1)
        part += __shfl_down_sync(mask, part, o);
    __shared__ double sred2[8];
    if (lane == 0) sred2[warp] = part;
    __syncthreads();
    if (t == 0) {
        double s = 0.0;
        for (int wi = 0; wi < nwarps; wi++) s += sred2[wi];
        g_num1[b] = s;
    }
}

// ---------------------------------------------------------------------------
// Kernel 2: pairwise bond term, upper-triangular tiles only (symmetry),
// off-diagonal tiles doubled. One MUFU sqrt per pair via
// (dp - dg)^2 = dp2 + dg2 - 2*sqrt(dp2*dg2).
// ---------------------------------------------------------------------------
#define PAIR_THREADS 128
#define TI 256
#define TJ 256

__global__ void __launch_bounds__(PAIR_THREADS)
pair_kernel(const float* __restrict__ pred,
            const float* __restrict__ gt,
            const float* __restrict__ w,
            int N, int tilesI, int ntri)
{
    int blk = blockIdx.x;
    int b   = blk / ntri;
    int rem = blk % ntri;
    // decode triangular (ti, tj) with tj >= ti
    int ti = 0, rowlen = tilesI;
    while (rem >= rowlen) { rem -= rowlen; ti++; rowlen--; }
    int tj = ti + rem;

    const float* pb = pred + (size_t)b * N * 3;
    const float* gb = gt   + (size_t)b * N * 3;
    const float* wb = w    + (size_t)b * N;

    __shared__ float4 spj[TJ];   // pred_j + w_j
    __shared__ float4 sgj[TJ];   // gt_j

    const int t = threadIdx.x;
    for (int k = t; k < TJ; k += PAIR_THREADS) {
        int j = tj * TJ + k;
        float4 p4 = make_float4(0.f, 0.f, 0.f, 0.f);
        float4 g4 = make_float4(0.f, 0.f, 0.f, 0.f);
        if (j < N) {
            p4.x = pb[3*j]; p4.y = pb[3*j+1]; p4.z = pb[3*j+2]; p4.w = wb[j];
            g4.x = gb[3*j]; g4.y = gb[3*j+1]; g4.z = gb[3*j+2];
        }
        spj[k] = p4;
        sgj[k] = g4;
    }

    int i0 = ti * TI + t;
    int i1 = i0 + PAIR_THREADS;
    float p0x=0.f,p0y=0.f,p0z=0.f,g0x=0.f,g0y=0.f,g0z=0.f,w0=0.f;
    float p1x=0.f,p1y=0.f,p1z=0.f,g1x=0.f,g1y=0.f,g1z=0.f,w1=0.f;
    if (i0 < N) {
        p0x = pb[3*i0]; p0y = pb[3*i0+1]; p0z = pb[3*i0+2]; w0 = wb[i0];
        g0x = gb[3*i0]; g0y = gb[3*i0+1]; g0z = gb[3*i0+2];
    }
    if (i1 < N) {
        p1x = pb[3*i1]; p1y = pb[3*i1+1]; p1z = pb[3*i1+2]; w1 = wb[i1];
        g1x = gb[3*i1]; g1y = gb[3*i1+1]; g1z = gb[3*i1+2];
    }
    __syncthreads();

    float acc0 = 0.f, acc1 = 0.f;
#pragma unroll 4
    for (int k = 0; k < TJ; k++) {
        float4 pj = spj[k];
        float4 gj = sgj[k];
        {
            float dx = p0x - pj.x, dy = p0y - pj.y, dz = p0z - pj.z;
            float dp2 = dx*dx + dy*dy + dz*dz;
            float ex = g0x - gj.x, ey = g0y - gj.y, ez = g0z - gj.z;
            float dg2 = ex*ex + ey*ey + ez*ez;
            float s = fsqrt_approx(dp2 * dg2);
            float term = dp2 + dg2 - 2.f * s;
            acc0 = fmaf(w0 * pj.w, term, acc0);
        }
        {
            float dx = p1x - pj.x, dy = p1y - pj.y, dz = p1z - pj.z;
            float dp2 = dx*dx + dy*dy + dz*dz;
            float ex = g1x - gj.x, ey = g1y - gj.y, ez = g1z - gj.z;
            float dg2 = ex*ex + ey*ey + ez*ez;
            float s = fsqrt_approx(dp2 * dg2);
            float term = dp2 + dg2 - 2.f * s;
            acc1 = fmaf(w1 * pj.w, term, acc1);
        }
    }

    double tot = (double)acc0 + (double)acc1;
    if (ti != tj) tot *= 2.0;     // symmetry: count (j,i) too
    const unsigned mask = 0xffffffffu;
    for (int o = 16; o > 0; o >>= 1)
        tot += __shfl_down_sync(mask, tot, o);
    __shared__ double sredp[PAIR_THREADS/32];
    int warp = t >> 5, lane = t & 31;
    if (lane == 0) sredp[warp] = tot;
    __syncthreads();
    if (t == 0) {
        double s = 0.0;
        for (int wi = 0; wi < PAIR_THREADS/32; wi++) s += sredp[wi];
        atomicAdd(&g_bond, s);
    }
}

// ---------------------------------------------------------------------------
// Kernel 3: final scalar combination + per-batch ht scaling.
// ---------------------------------------------------------------------------
__global__ void final_kernel(const float* __restrict__ ht,
                             float* __restrict__ out, int B)
{
    if (threadIdx.x == 0 && blockIdx.x == 0) {
        double sw = 0.0, sw2 = 0.0, sn = 0.0;
        for (int b = 0; b < B; b++) {
            double W = g_W[b];
            sw += W; sw2 += W * W; sn += g_num1[b];
        }
        double loss = sn / sw + g_bond / sw2;   // ALPHA_BOND = 1
        for (int b = 0; b < B; b++) {
            double h = (double)ht[b];
            out[b] = (float)(((h*h + 256.0) / ((h + 16.0) * (h + 16.0))) * loss);
        }
    }
}

extern "C" void kernel_launch(void* const* d_in, const int* in_sizes, int n_in,
                              void* d_out, int out_size)
{
    const float* pred = (const float*)d_in[0];
    const float* gt   = (const float*)d_in[1];
    const float* ht   = (const float*)d_in[2];
    const float* w    = (const float*)d_in[3];
    int B = in_sizes[2];
    int N = in_sizes[3] / B;

    stats_align_kernel<<<B, 256>>>(pred, gt, w, N);

    int tilesI = (N + TI - 1) / TI;
    int ntri = tilesI * (tilesI + 1) / 2;
    pair_kernel<<<B * ntri, PAIR_THREADS>>>(pred, gt, w, N, tilesI, ntri);

    final_kernel<<<1, 32>>>(ht, (float*)d_out, B);
}

// round 3
// speedup vs baseline: 3.3520x; 1.0782x over previous
#include <cuda_runtime.h>
#include <math.h>

// ---------------------------------------------------------------------------
// DiffusionLoss (AF3-style): Kabsch-align GT onto pred, weighted coord loss +
// pairwise distance ("bond") loss, scaled per-batch by (ht^2+sd^2)/(ht+sd)^2.
// Inputs: xpred [B,N,3] f32, xGT [B,N,3] f32, ht [B] f32, w [B,N] f32.
// Output: [B] f32.
//
// Pipeline (3 launches):
//   K1 reduce_solve : wide stats reduction; last block per batch does 3x3
//                     Kabsch solve and zeroes accumulators.
//   K2 pair_kernel  : triangular pairwise bond tiles; diagonal tiles also
//                     compute the per-atom alignment loss (fused).
//   K3 final_kernel : scalar combine + per-batch ht scaling.
// ---------------------------------------------------------------------------

#define MAXB 16
#define MAXBLK 64          // max reduce blocks per batch (N <= 16384)

__device__ double g_part[MAXB][MAXBLK][16];  // per-block stats partials
__device__ unsigned g_cnt[MAXB];             // arrive counters (wrap -> replay safe)
__device__ float  g_par[MAXB][15];           // R[9], mu[3], muGT[3]
__device__ double g_W[MAXB];                 // per-batch sum of weights
__device__ double g_num1[MAXB];              // alignment-loss numerators
__device__ double g_bond;                    // bond-loss numerator

__device__ __forceinline__ float fsqrt_approx(float x) {
    float r;
    asm("sqrt.approx.f32 %0, %1;" : "=f"(r) : "f"(x));
    return r;
}

// ---------------------------------------------------------------------------
// K1: stats reduction + last-block 3x3 Kabsch solve.
// grid = B * blocksPerB, 256 threads. One atom row per thread.
// ---------------------------------------------------------------------------
__global__ void __launch_bounds__(256)
reduce_solve_kernel(const float* __restrict__ pred,
                    const float* __restrict__ gt,
                    const float* __restrict__ w,
                    int N, int blocksPerB)
{
    const int b   = blockIdx.x / blocksPerB;
    const int blk = blockIdx.x % blocksPerB;
    const int t   = threadIdx.x;
    const float* pb = pred + (size_t)b * N * 3;
    const float* gb = gt   + (size_t)b * N * 3;
    const float* wb = w    + (size_t)b * N;

    // acc: [0]=W, [1..3]=sum w*p, [4..6]=sum w*g, [7..15]=sum w*p_i*g_j
    float acc[16];
#pragma unroll
    for (int i = 0; i < 16; i++) acc[i] = 0.f;

    for (int n = blk * blockDim.x + t; n < N; n += blocksPerB * blockDim.x) {
        float wn = wb[n];
        float px = pb[3*n], py = pb[3*n+1], pz = pb[3*n+2];
        float gx = gb[3*n], gy = gb[3*n+1], gz = gb[3*n+2];
        float wpx = wn*px, wpy = wn*py, wpz = wn*pz;
        acc[0]  += wn;
        acc[1]  += wpx;   acc[2]  += wpy;   acc[3]  += wpz;
        acc[4]  += wn*gx; acc[5]  += wn*gy; acc[6]  += wn*gz;
        acc[7]  += wpx*gx; acc[8]  += wpx*gy; acc[9]  += wpx*gz;
        acc[10] += wpy*gx; acc[11] += wpy*gy; acc[12] += wpy*gz;
        acc[13] += wpz*gx; acc[14] += wpz*gy; acc[15] += wpz*gz;
    }

    const unsigned mask = 0xffffffffu;
    double accd[16];
#pragma unroll
    for (int i = 0; i < 16; i++) accd[i] = (double)acc[i];
#pragma unroll
    for (int i = 0; i < 16; i++)
        for (int o = 16; o > 0; o >>= 1)
            accd[i] += __shfl_down_sync(mask, accd[i], o);

    __shared__ double sred[8][16];
    int warp = t >> 5, lane = t & 31;
    if (lane == 0)
#pragma unroll
        for (int i = 0; i < 16; i++) sred[warp][i] = accd[i];
    __syncthreads();

    __shared__ int sIsLast;
    if (t == 0) {
        double v[16];
#pragma unroll
        for (int i = 0; i < 16; i++) {
            double s = 0.0;
            for (int wi = 0; wi < 8; wi++) s += sred[wi][i];
            g_part[b][blk][i] = s;
        }
        __threadfence();
        unsigned old = atomicInc(&g_cnt[b], (unsigned)(blocksPerB - 1));
        sIsLast = (old == (unsigned)(blocksPerB - 1));
    }
    __syncthreads();
    if (!sIsLast || t != 0) return;

    // ----- last block, thread 0: deterministic final sum + Kabsch solve -----
    __threadfence();
    double v[16];
    for (int i = 0; i < 16; i++) {
        double s = 0.0;
        for (int k = 0; k < blocksPerB; k++) s += g_part[b][k][i];
        v[i] = s;
    }
    double W = v[0];
    double invW = 1.0 / W;
    // mu = GT weighted mean, muGT = pred mean (arg-swap in reference)
    float muGT[3] = { (float)(v[1]*invW), (float)(v[2]*invW), (float)(v[3]*invW) };
    float mu[3]   = { (float)(v[4]*invW), (float)(v[5]*invW), (float)(v[6]*invW) };

    float A[3][3];
    for (int i = 0; i < 3; i++)
        for (int j = 0; j < 3; j++)
            A[i][j] = (float)(v[7 + i*3 + j] - v[1+i]*v[4+j]*invW);

    float detA = A[0][0]*(A[1][1]*A[2][2]-A[1][2]*A[2][1])
               - A[0][1]*(A[1][0]*A[2][2]-A[1][2]*A[2][0])
               + A[0][2]*(A[1][0]*A[2][1]-A[1][1]*A[2][0]);

    float C[3][3];
    for (int i = 0; i < 3; i++)
        for (int j = 0; j < 3; j++) {
            float s = 0.f;
            for (int k = 0; k < 3; k++) s += A[k][i]*A[k][j];
            C[i][j] = s;
        }
    float V[3][3] = {{1,0,0},{0,1,0},{0,0,1}};
#pragma unroll
    for (int sweep = 0; sweep < 6; sweep++) {
#pragma unroll
        for (int p = 0; p < 3; p++)
#pragma unroll
            for (int q = p+1; q < 3; q++) {
                float apq = C[p][q];
                if (apq == 0.f) continue;
                float theta = __fdividef(C[q][q] - C[p][p], 2.f * apq);
                float tt = (theta >= 0.f ? 1.f : -1.f) *
                           __fdividef(1.f, fabsf(theta) + sqrtf(theta*theta + 1.f));
                float c = rsqrtf(tt*tt + 1.f), s = tt * c;
                for (int k = 0; k < 3; k++) {
                    float a = C[k][p], bb = C[k][q];
                    C[k][p] = c*a - s*bb;  C[k][q] = s*a + c*bb;
                }
                for (int k = 0; k < 3; k++) {
                    float a = C[p][k], bb = C[q][k];
                    C[p][k] = c*a - s*bb;  C[q][k] = s*a + c*bb;
                }
                for (int k = 0; k < 3; k++) {
                    float a = V[k][p], bb = V[k][q];
                    V[k][p] = c*a - s*bb;  V[k][q] = s*a + c*bb;
                }
            }
    }
    float eig[3] = { C[0][0], C[1][1], C[2][2] };
    int idx[3] = {0, 1, 2};
    for (int i = 0; i < 2; i++)
        for (int j = i+1; j < 3; j++)
            if (eig[idx[j]] > eig[idx[i]]) { int tmp = idx[i]; idx[i] = idx[j]; idx[j] = tmp; }

    float emax = fmaxf(eig[idx[0]], 0.f);
    float dinv[3];
    for (int i = 0; i < 3; i++) {
        float e = fmaxf(eig[idx[i]], 0.f);
        dinv[i] = (e > 1e-12f * emax && e > 0.f) ? rsqrtf(e) : 0.f;
    }
    if (detA < 0.f) dinv[2] = -dinv[2];

    float T[3][3];
    for (int i = 0; i < 3; i++)
        for (int j = 0; j < 3; j++) {
            float s = 0.f;
            for (int k = 0; k < 3; k++) s += A[i][k] * V[k][idx[j]];
            T[i][j] = s * dinv[j];
        }
    for (int i = 0; i < 3; i++)
        for (int j = 0; j < 3; j++) {
            float s = 0.f;
            for (int k = 0; k < 3; k++) s += T[i][k] * V[j][idx[k]];
            g_par[b][i*3 + j] = s;
        }
    g_par[b][9]  = mu[0];   g_par[b][10] = mu[1];   g_par[b][11] = mu[2];
    g_par[b][12] = muGT[0]; g_par[b][13] = muGT[1]; g_par[b][14] = muGT[2];
    g_W[b]    = W;
    g_num1[b] = 0.0;
    if (b == 0) g_bond = 0.0;
    __threadfence();
}

// ---------------------------------------------------------------------------
// K2: pairwise bond tiles (upper-triangular, off-diag doubled) + alignment
// loss fused into diagonal tiles. 256 threads, one i-row per thread.
// (dp - dg)^2 = dp2 + dg2 - 2*sqrt(dp2*dg2) -> one MUFU per pair.
// ---------------------------------------------------------------------------
#define PAIR_THREADS 256
#define TI 256
#define TJ 256

__global__ void __launch_bounds__(PAIR_THREADS)
pair_kernel(const float* __restrict__ pred,
            const float* __restrict__ gt,
            const float* __restrict__ w,
            int N, int tilesI, int ntri)
{
    int blk = blockIdx.x;
    int b   = blk / ntri;
    int rem = blk % ntri;
    int ti = 0, rowlen = tilesI;
    while (rem >= rowlen) { rem -= rowlen; ti++; rowlen--; }
    int tj = ti + rem;

    const float* pb = pred + (size_t)b * N * 3;
    const float* gb = gt   + (size_t)b * N * 3;
    const float* wb = w    + (size_t)b * N;

    __shared__ float4 spj[TJ];
    __shared__ float4 sgj[TJ];

    const int t = threadIdx.x;
    {
        int j = tj * TJ + t;
        float4 p4 = make_float4(0.f, 0.f, 0.f, 0.f);
        float4 g4 = make_float4(0.f, 0.f, 0.f, 0.f);
        if (j < N) {
            p4.x = pb[3*j]; p4.y = pb[3*j+1]; p4.z = pb[3*j+2]; p4.w = wb[j];
            g4.x = gb[3*j]; g4.y = gb[3*j+1]; g4.z = gb[3*j+2];
        }
        spj[t] = p4;
        sgj[t] = g4;
    }

    int i0 = ti * TI + t;
    float p0x=0.f,p0y=0.f,p0z=0.f,g0x=0.f,g0y=0.f,g0z=0.f,w0=0.f;
    if (i0 < N) {
        p0x = pb[3*i0]; p0y = pb[3*i0+1]; p0z = pb[3*i0+2]; w0 = wb[i0];
        g0x = gb[3*i0]; g0y = gb[3*i0+1]; g0z = gb[3*i0+2];
    }
    __syncthreads();

    float acc0 = 0.f;
#pragma unroll 8
    for (int k = 0; k < TJ; k++) {
        float4 pj = spj[k];
        float4 gj = sgj[k];
        float dx = p0x - pj.x, dy = p0y - pj.y, dz = p0z - pj.z;
        float dp2 = dx*dx + dy*dy + dz*dz;
        float ex = g0x - gj.x, ey = g0y - gj.y, ez = g0z - gj.z;
        float dg2 = ex*ex + ey*ey + ez*ez;
        float s = fsqrt_approx(dp2 * dg2);
        float term = dp2 + dg2 - 2.f * s;
        acc0 = fmaf(w0 * pj.w, term, acc0);
    }

    double tot = (double)acc0;
    if (ti != tj) tot *= 2.0;     // symmetry
    const unsigned mask = 0xffffffffu;
    for (int o = 16; o > 0; o >>= 1)
        tot += __shfl_down_sync(mask, tot, o);
    __shared__ double sredp[PAIR_THREADS/32];
    int warp = t >> 5, lane = t & 31;
    if (lane == 0) sredp[warp] = tot;

    // ---- fused alignment loss on diagonal tiles ----
    if (ti == tj) {
        float R00 = g_par[b][0], R01 = g_par[b][1], R02 = g_par[b][2];
        float R10 = g_par[b][3], R11 = g_par[b][4], R12 = g_par[b][5];
        float R20 = g_par[b][6], R21 = g_par[b][7], R22 = g_par[b][8];
        float mux = g_par[b][9],  muy = g_par[b][10], muz = g_par[b][11];
        float mgx = g_par[b][12], mgy = g_par[b][13], mgz = g_par[b][14];

        float gx = g0x - mux, gy = g0y - muy, gz = g0z - muz;
        float ax = R00*gx + R01*gy + R02*gz + mgx;
        float ay = R10*gx + R11*gy + R12*gz + mgy;
        float az = R20*gx + R21*gy + R22*gz + mgz;
        float dx = p0x - ax, dy = p0y - ay, dz = p0z - az;
        float sq = dx*dx + dy*dy + dz*dz;
        double al = (double)(w0 * fsqrt_approx(sq));
        for (int o = 16; o > 0; o >>= 1)
            al += __shfl_down_sync(mask, al, o);
        __shared__ double sreda[PAIR_THREADS/32];
        if (lane == 0) sreda[warp] = al;
        __syncthreads();
        if (t == 0) {
            double s = 0.0;
            for (int wi = 0; wi < PAIR_THREADS/32; wi++) s += sreda[wi];
            atomicAdd(&g_num1[b], s);
        }
    } else {
        __syncthreads();
    }

    if (t == 0) {
        double s = 0.0;
        for (int wi = 0; wi < PAIR_THREADS/32; wi++) s += sredp[wi];
        atomicAdd(&g_bond, s);
    }
}

// ---------------------------------------------------------------------------
// K3: final scalar combination + per-batch ht scaling.
// ---------------------------------------------------------------------------
__global__ void final_kernel(const float* __restrict__ ht,
                             float* __restrict__ out, int B)
{
    if (threadIdx.x == 0 && blockIdx.x == 0) {
        double sw = 0.0, sw2 = 0.0, sn = 0.0;
        for (int b = 0; b < B; b++) {
            double W = g_W[b];
            sw += W; sw2 += W * W; sn += g_num1[b];
        }
        double loss = sn / sw + g_bond / sw2;   // ALPHA_BOND = 1
        for (int b = 0; b < B; b++) {
            double h = (double)ht[b];
            out[b] = (float)(((h*h + 256.0) / ((h + 16.0) * (h + 16.0))) * loss);
        }
    }
}

extern "C" void kernel_launch(void* const* d_in, const int* in_sizes, int n_in,
                              void* d_out, int out_size)
{
    const float* pred = (const float*)d_in[0];
    const float* gt   = (const float*)d_in[1];
    const float* ht   = (const float*)d_in[2];
    const float* w    = (const float*)d_in[3];
    int B = in_sizes[2];
    int N = in_sizes[3] / B;

    int blocksPerB = (N + 255) / 256;
    if (blocksPerB > MAXBLK) blocksPerB = MAXBLK;
    reduce_solve_kernel<<<B * blocksPerB, 256>>>(pred, gt, w, N, blocksPerB);

    int tilesI = (N + TI - 1) / TI;
    int ntri = tilesI * (tilesI + 1) / 2;
    pair_kernel<<<B * ntri, PAIR_THREADS>>>(pred, gt, w, N, tilesI, ntri);

    final_kernel<<<1, 32>>>(ht, (float*)d_out, B);
}

// round 4
// speedup vs baseline: 4.1199x; 1.2291x over previous
#include <cuda_runtime.h>
#include <math.h>

// ---------------------------------------------------------------------------
// DiffusionLoss fused single-kernel implementation.
// grid = B * ntri tile-blocks (<=148 -> all co-resident, intra-grid sync OK):
//   - diagonal-tile blocks (first B*tilesI block ids): stats partials ->
//     last per batch does 3x3 Kabsch solve -> release flag
//   - all blocks: triangular pairwise bond tiles (13 FMA-ops + 1 MUFU / pair)
//   - diagonal blocks: spin on flag (usually ready), fused alignment loss
//   - globally last block: final combine, write out, reset state (replayable)
// Fallback (grid > 148): separate reduce_solve kernel + fused(precomputed=1).
// ---------------------------------------------------------------------------

#define MAXB 16
#define MAXBLK 64
#define TILE 256

__device__ double   g_part[MAXB][MAXBLK][16];
__device__ unsigned g_cnt[MAXB];      // per-batch stats arrival (wrap)
__device__ int      g_ready[MAXB];    // solve-done flag (reset by final block)
__device__ float    g_par[MAXB][15];  // R[9], mu[3], muGT[3]
__device__ double   g_W[MAXB];
__device__ double   g_num1[MAXB];
__device__ double   g_bond;
__device__ unsigned g_done;           // global arrival counter (wrap)

__device__ __forceinline__ float fsqrt_approx(float x) {
    float r;
    asm("sqrt.approx.f32 %0, %1;" : "=f"(r) : "f"(x));
    return r;
}

// ---------------------------------------------------------------------------
// 3x3 Kabsch solve from accumulated moments v[16] (thread-serial, float).
// ---------------------------------------------------------------------------
__device__ void kabsch_solve(const double* v, int b)
{
    double W = v[0];
    double invW = 1.0 / W;
    // mu = GT weighted mean, muGT = pred mean (arg-swap in reference)
    float muGT[3] = { (float)(v[1]*invW), (float)(v[2]*invW), (float)(v[3]*invW) };
    float mu[3]   = { (float)(v[4]*invW), (float)(v[5]*invW), (float)(v[6]*invW) };

    float A[3][3];
    for (int i = 0; i < 3; i++)
        for (int j = 0; j < 3; j++)
            A[i][j] = (float)(v[7 + i*3 + j] - v[1+i]*v[4+j]*invW);

    float detA = A[0][0]*(A[1][1]*A[2][2]-A[1][2]*A[2][1])
               - A[0][1]*(A[1][0]*A[2][2]-A[1][2]*A[2][0])
               + A[0][2]*(A[1][0]*A[2][1]-A[1][1]*A[2][0]);

    float C[3][3];
    for (int i = 0; i < 3; i++)
        for (int j = 0; j < 3; j++) {
            float s = 0.f;
            for (int k = 0; k < 3; k++) s += A[k][i]*A[k][j];
            C[i][j] = s;
        }
    float V[3][3] = {{1,0,0},{0,1,0},{0,0,1}};
#pragma unroll
    for (int sweep = 0; sweep < 6; sweep++) {
#pragma unroll
        for (int p = 0; p < 3; p++)
#pragma unroll
            for (int q = p+1; q < 3; q++) {
                float apq = C[p][q];
                if (apq == 0.f) continue;
                float theta = __fdividef(C[q][q] - C[p][p], 2.f * apq);
                float tt = (theta >= 0.f ? 1.f : -1.f) *
                           __fdividef(1.f, fabsf(theta) + sqrtf(theta*theta + 1.f));
                float c = rsqrtf(tt*tt + 1.f), s = tt * c;
                for (int k = 0; k < 3; k++) {
                    float a = C[k][p], bb = C[k][q];
                    C[k][p] = c*a - s*bb;  C[k][q] = s*a + c*bb;
                }
                for (int k = 0; k < 3; k++) {
                    float a = C[p][k], bb = C[q][k];
                    C[p][k] = c*a - s*bb;  C[q][k] = s*a + c*bb;
                }
                for (int k = 0; k < 3; k++) {
                    float a = V[k][p], bb = V[k][q];
                    V[k][p] = c*a - s*bb;  V[k][q] = s*a + c*bb;
                }
            }
    }
    float eig[3] = { C[0][0], C[1][1], C[2][2] };
    int idx[3] = {0, 1, 2};
    for (int i = 0; i < 2; i++)
        for (int j = i+1; j < 3; j++)
            if (eig[idx[j]] > eig[idx[i]]) { int tmp = idx[i]; idx[i] = idx[j]; idx[j] = tmp; }

    float emax = fmaxf(eig[idx[0]], 0.f);
    float dinv[3];
    for (int i = 0; i < 3; i++) {
        float e = fmaxf(eig[idx[i]], 0.f);
        dinv[i] = (e > 1e-12f * emax && e > 0.f) ? rsqrtf(e) : 0.f;
    }
    if (detA < 0.f) dinv[2] = -dinv[2];

    float T[3][3];
    for (int i = 0; i < 3; i++)
        for (int j = 0; j < 3; j++) {
            float s = 0.f;
            for (int k = 0; k < 3; k++) s += A[i][k] * V[k][idx[j]];
            T[i][j] = s * dinv[j];
        }
    for (int i = 0; i < 3; i++)
        for (int j = 0; j < 3; j++) {
            float s = 0.f;
            for (int k = 0; k < 3; k++) s += T[i][k] * V[j][idx[k]];
            g_par[b][i*3 + j] = s;
        }
    g_par[b][9]  = mu[0];   g_par[b][10] = mu[1];   g_par[b][11] = mu[2];
    g_par[b][12] = muGT[0]; g_par[b][13] = muGT[1]; g_par[b][14] = muGT[2];
    g_W[b] = W;
}

// ---------------------------------------------------------------------------
// Fallback K1 (only used when fused grid would exceed one wave).
// ---------------------------------------------------------------------------
__global__ void __launch_bounds__(256)
reduce_solve_kernel(const float* __restrict__ pred,
                    const float* __restrict__ gt,
                    const float* __restrict__ w,
                    int N, int blocksPerB)
{
    const int b   = blockIdx.x / blocksPerB;
    const int blk = blockIdx.x % blocksPerB;
    const int t   = threadIdx.x;
    const float* pb = pred + (size_t)b * N * 3;
    const float* gb = gt   + (size_t)b * N * 3;
    const float* wb = w    + (size_t)b * N;

    float acc[16];
#pragma unroll
    for (int i = 0; i < 16; i++) acc[i] = 0.f;
    for (int n = blk * blockDim.x + t; n < N; n += blocksPerB * blockDim.x) {
        float wn = wb[n];
        float px = pb[3*n], py = pb[3*n+1], pz = pb[3*n+2];
        float gx = gb[3*n], gy = gb[3*n+1], gz = gb[3*n+2];
        float wpx = wn*px, wpy = wn*py, wpz = wn*pz;
        acc[0] += wn;
        acc[1] += wpx;  acc[2] += wpy;  acc[3] += wpz;
        acc[4] += wn*gx; acc[5] += wn*gy; acc[6] += wn*gz;
        acc[7] += wpx*gx; acc[8] += wpx*gy; acc[9] += wpx*gz;
        acc[10] += wpy*gx; acc[11] += wpy*gy; acc[12] += wpy*gz;
        acc[13] += wpz*gx; acc[14] += wpz*gy; acc[15] += wpz*gz;
    }
    const unsigned mask = 0xffffffffu;
#pragma unroll
    for (int i = 0; i < 16; i++)
        for (int o = 16; o > 0; o >>= 1)
            acc[i] += __shfl_down_sync(mask, acc[i], o);
    __shared__ double sred[8][16];
    int warp = t >> 5, lane = t & 31;
    if (lane == 0)
#pragma unroll
        for (int i = 0; i < 16; i++) sred[warp][i] = (double)acc[i];
    __syncthreads();
    if (t != 0) return;
    double v[16];
#pragma unroll
    for (int i = 0; i < 16; i++) {
        double s = 0.0;
        for (int wi = 0; wi < 8; wi++) s += sred[wi][i];
        g_part[b][blk][i] = s;
    }
    __threadfence();
    unsigned old = atomicInc(&g_cnt[b], (unsigned)(blocksPerB - 1));
    if (old != (unsigned)(blocksPerB - 1)) return;
    __threadfence();
    double vv[16];
    for (int i = 0; i < 16; i++) {
        double s = 0.0;
        for (int k = 0; k < blocksPerB; k++) s += g_part[b][k][i];
        vv[i] = s;
    }
    kabsch_solve(vv, b);
    g_num1[b] = 0.0;
    if (b == 0) g_bond = 0.0;
    __threadfence();
}

// ---------------------------------------------------------------------------
// Fused kernel.
// ---------------------------------------------------------------------------
__global__ void __launch_bounds__(256)
fused_kernel(const float* __restrict__ pred,
             const float* __restrict__ gt,
             const float* __restrict__ w,
             const float* __restrict__ ht,
             float* __restrict__ out,
             int N, int B, int tilesI, int ntri, int precomputed)
{
    const int t = threadIdx.x;
    const int nOff = ntri - tilesI;
    const int blk = blockIdx.x;

    int b, ti, tj;
    bool diag;
    if (blk < B * tilesI) {                 // diagonal tiles first (wave-1)
        diag = true;
        b = blk / tilesI;
        ti = tj = blk % tilesI;
    } else {
        diag = false;
        int rem = blk - B * tilesI;
        b = rem / nOff;
        int r2 = rem % nOff;
        ti = 0;
        int rowlen = tilesI - 1;
        while (r2 >= rowlen) { r2 -= rowlen; ti++; rowlen--; }
        tj = ti + 1 + r2;
    }

    const float* pb = pred + (size_t)b * N * 3;
    const float* gb = gt   + (size_t)b * N * 3;
    const float* wb = w    + (size_t)b * N;

    __shared__ float4 spj[TILE];   // px,py,pz,|p|^2
    __shared__ float4 sgj[TILE];   // gx,gy,gz,|g|^2
    __shared__ float  swj[TILE];   // w_j
    __shared__ double sred[8][16];
    __shared__ int    sFlag;

    // ---- load j tile into shared ----
    {
        int j = tj * TILE + t;
        float4 p4 = make_float4(0.f, 0.f, 0.f, 0.f);
        float4 g4 = make_float4(0.f, 0.f, 0.f, 0.f);
        float wj = 0.f;
        if (j < N) {
            p4.x = pb[3*j]; p4.y = pb[3*j+1]; p4.z = pb[3*j+2];
            g4.x = gb[3*j]; g4.y = gb[3*j+1]; g4.z = gb[3*j+2];
            wj = wb[j];
            p4.w = p4.x*p4.x + p4.y*p4.y + p4.z*p4.z;
            g4.w = g4.x*g4.x + g4.y*g4.y + g4.z*g4.z;
        }
        spj[t] = p4; sgj[t] = g4; swj[t] = wj;
    }

    // ---- load i row into registers ----
    int i0 = ti * TILE + t;
    float p0x=0.f,p0y=0.f,p0z=0.f,g0x=0.f,g0y=0.f,g0z=0.f,w0=0.f;
    if (i0 < N) {
        p0x = pb[3*i0]; p0y = pb[3*i0+1]; p0z = pb[3*i0+2]; w0 = wb[i0];
        g0x = gb[3*i0]; g0y = gb[3*i0+1]; g0z = gb[3*i0+2];
    }
    float pn2_0 = p0x*p0x + p0y*p0y + p0z*p0z;
    float gn2_0 = g0x*g0x + g0y*g0y + g0z*g0z;
    float a0x = -2.f*p0x, a0y = -2.f*p0y, a0z = -2.f*p0z;
    float c0x = -2.f*g0x, c0y = -2.f*g0y, c0z = -2.f*g0z;

    const unsigned mask = 0xffffffffu;
    int warp = t >> 5, lane = t & 31;

    // ---- stats partial (diagonal blocks own exactly their 256 atoms) ----
    if (diag && !precomputed) {
        float acc[16];
        float wpx = w0*p0x, wpy = w0*p0y, wpz = w0*p0z;
        acc[0] = w0;
        acc[1] = wpx;    acc[2] = wpy;    acc[3] = wpz;
        acc[4] = w0*g0x; acc[5] = w0*g0y; acc[6] = w0*g0z;
        acc[7] = wpx*g0x; acc[8] = wpx*g0y; acc[9] = wpx*g0z;
        acc[10] = wpy*g0x; acc[11] = wpy*g0y; acc[12] = wpy*g0z;
        acc[13] = wpz*g0x; acc[14] = wpz*g0y; acc[15] = wpz*g0z;
#pragma unroll
        for (int i = 0; i < 16; i++)
            for (int o = 16; o > 0; o >>= 1)
                acc[i] += __shfl_down_sync(mask, acc[i], o);
        if (lane == 0)
#pragma unroll
            for (int i = 0; i < 16; i++) sred[warp][i] = (double)acc[i];
    }
    __syncthreads();   // covers shared tile fill AND sred writes

    if (diag && !precomputed && t == 0) {
        double v[16];
#pragma unroll
        for (int i = 0; i < 16; i++) {
            double s = 0.0;
            for (int wi = 0; wi < 8; wi++) s += sred[wi][i];
            g_part[b][ti][i] = s;
        }
        __threadfence();
        unsigned old = atomicInc(&g_cnt[b], (unsigned)(tilesI - 1));
        if (old == (unsigned)(tilesI - 1)) {
            __threadfence();
            double vv[16];
            for (int i = 0; i < 16; i++) {
                double s = 0.0;
                for (int k = 0; k < tilesI; k++) s += g_part[b][k][i];
                vv[i] = s;
            }
            kabsch_solve(vv, b);
            __threadfence();
            atomicExch(&g_ready[b], 1);
        }
    }

    // ---- bond tile: 13 FMA-pipe ops + 1 MUFU per pair ----
    float acc0 = 0.f;
#pragma unroll 8
    for (int k = 0; k < TILE; k++) {
        float4 pj = spj[k];
        float4 gj = sgj[k];
        float wj = swj[k];
        float dp2 = fmaf(a0z, pj.z, fmaf(a0y, pj.y, fmaf(a0x, pj.x, pn2_0 + pj.w)));
        float dg2 = fmaf(c0z, gj.z, fmaf(c0y, gj.y, fmaf(c0x, gj.x, gn2_0 + gj.w)));
        float prod = fmaxf(dp2 * dg2, 0.f);
        float s = fsqrt_approx(prod);
        float term = fmaf(-2.f, s, dp2 + dg2);
        acc0 = fmaf(wj, term, acc0);
    }
    acc0 *= w0;

    double tot = (double)acc0;
    if (!diag) tot *= 2.0;         // symmetry
    for (int o = 16; o > 0; o >>= 1)
        tot += __shfl_down_sync(mask, tot, o);
    __shared__ double sredp[8];
    if (lane == 0) sredp[warp] = tot;

    // ---- fused alignment loss (diagonal blocks only) ----
    if (diag) {
        if (!precomputed) {
            if (t == 0) {
                while (atomicAdd(&g_ready[b], 0) == 0) {}
                __threadfence();
                sFlag = 1;
            }
        }
        __syncthreads();
        float R00 = g_par[b][0], R01 = g_par[b][1], R02 = g_par[b][2];
        float R10 = g_par[b][3], R11 = g_par[b][4], R12 = g_par[b][5];
        float R20 = g_par[b][6], R21 = g_par[b][7], R22 = g_par[b][8];
        float mux = g_par[b][9],  muy = g_par[b][10], muz = g_par[b][11];
        float mgx = g_par[b][12], mgy = g_par[b][13], mgz = g_par[b][14];

        float gx = g0x - mux, gy = g0y - muy, gz = g0z - muz;
        float ax = R00*gx + R01*gy + R02*gz + mgx;
        float ay = R10*gx + R11*gy + R12*gz + mgy;
        float az = R20*gx + R21*gy + R22*gz + mgz;
        float dx = p0x - ax, dy = p0y - ay, dz = p0z - az;
        float sq = dx*dx + dy*dy + dz*dz;
        double al = (double)(w0 * fsqrt_approx(sq));
        for (int o = 16; o > 0; o >>= 1)
            al += __shfl_down_sync(mask, al, o);
        __shared__ double sreda[8];
        if (lane == 0) sreda[warp] = al;
        __syncthreads();
        if (t == 0) {
            double s = 0.0;
            for (int wi = 0; wi < 8; wi++) s += sreda[wi];
            atomicAdd(&g_num1[b], s);
        }
    } else {
        __syncthreads();
    }

    // ---- block totals + global completion ----
    if (t == 0) {
        double s = 0.0;
        for (int wi = 0; wi < 8; wi++) s += sredp[wi];
        atomicAdd(&g_bond, s);
        __threadfence();
        unsigned old = atomicInc(&g_done, (unsigned)(gridDim.x - 1));
        if (old == (unsigned)(gridDim.x - 1)) {
            __threadfence();
            double sw = 0.0, sw2 = 0.0, sn = 0.0;
            for (int bb = 0; bb < B; bb++) {
                double W = g_W[bb];
                sw += W; sw2 += W * W; sn += g_num1[bb];
            }
            double loss = sn / sw + g_bond / sw2;   // ALPHA_BOND = 1
            for (int bb = 0; bb < B; bb++) {
                double h = (double)ht[bb];
                out[bb] = (float)(((h*h + 256.0) / ((h + 16.0) * (h + 16.0))) * loss);
            }
            // reset state for next graph replay
            g_bond = 0.0;
            for (int bb = 0; bb < B; bb++) { g_num1[bb] = 0.0; g_ready[bb] = 0; }
            __threadfence();
        }
    }
}

extern "C" void kernel_launch(void* const* d_in, const int* in_sizes, int n_in,
                              void* d_out, int out_size)
{
    const float* pred = (const float*)d_in[0];
    const float* gt   = (const float*)d_in[1];
    const float* ht   = (const float*)d_in[2];
    const float* w    = (const float*)d_in[3];
    int B = in_sizes[2];
    int N = in_sizes[3] / B;

    int tilesI = (N + TILE - 1) / TILE;
    int ntri = tilesI * (tilesI + 1) / 2;
    int grid = B * ntri;

    if (grid <= 148 && tilesI <= MAXBLK && B <= MAXB) {
        // fully fused: all blocks co-resident, intra-grid sync is safe
        fused_kernel<<<grid, 256>>>(pred, gt, w, ht, (float*)d_out,
                                    N, B, tilesI, ntri, 0);
    } else {
        // fallback: separate stats/solve pass, then fused without spin
        int blocksPerB = (N + 255) / 256;
        if (blocksPerB > MAXBLK) blocksPerB = MAXBLK;
        reduce_solve_kernel<<<B * blocksPerB, 256>>>(pred, gt, w, N, blocksPerB);
        fused_kernel<<<grid, 256>>>(pred, gt, w, ht, (float*)d_out,
                                    N, B, tilesI, ntri, 1);
    }
}

// round 5
// speedup vs baseline: 4.4804x; 1.0875x over previous
#include <cuda_runtime.h>
#include <math.h>

// ---------------------------------------------------------------------------
// DiffusionLoss fused single-kernel implementation (512 threads/block).
// grid = B * ntri tile-blocks (<=148 -> all co-resident):
//   - thread t handles i-row (t & 255) and j-half (t >> 8) of a 256x256 tile
//   - diagonal-tile blocks compute stats partials; last per batch solves the
//     3x3 Kabsch rotation and releases a flag (overlapped with bond compute)
//   - bond inner loop uses packed f32x2 math: dp2 & dg2 computed together
//   - diagonal blocks add the fused per-atom alignment loss
//   - globally last block combines, writes out, resets state (replay-safe)
// ---------------------------------------------------------------------------

#define MAXB 16
#define MAXBLK 64
#define TILE 256
#define NTHR 512

__device__ double   g_part[MAXB][MAXBLK][16];
__device__ unsigned g_cnt[MAXB];      // per-batch stats arrival (wrap)
__device__ int      g_ready[MAXB];    // solve-done flag
__device__ float    g_par[MAXB][15];  // R[9], mu[3], muGT[3]
__device__ double   g_W[MAXB];
__device__ double   g_num1[MAXB];
__device__ double   g_bond;
__device__ unsigned g_done;           // global arrival counter (wrap)

__device__ __forceinline__ float fsqrt_approx(float x) {
    float r;
    asm("sqrt.approx.f32 %0, %1;" : "=f"(r) : "f"(x));
    return r;
}

#define PACK_F32X2(out, lo, hi) \
    asm("mov.b64 %0, {%1, %2};" : "=l"(out) : "f"(lo), "f"(hi))
#define UNPACK_F32X2(lo, hi, in) \
    asm("mov.b64 {%0, %1}, %2;" : "=f"(lo), "=f"(hi) : "l"(in))
#define ADD_F32X2(out, a, b) \
    asm("add.rn.f32x2 %0, %1, %2;" : "=l"(out) : "l"(a), "l"(b))
#define FMA_F32X2(d, a, b, c) \
    asm("fma.rn.f32x2 %0, %1, %2, %3;" : "=l"(d) : "l"(a), "l"(b), "l"(c))

// ---------------------------------------------------------------------------
// 3x3 Kabsch solve from accumulated moments v[16] (thread-serial, float).
// ---------------------------------------------------------------------------
__device__ void kabsch_solve(const double* v, int b)
{
    double W = v[0];
    double invW = 1.0 / W;
    // mu = GT weighted mean, muGT = pred mean (arg-swap in reference)
    float muGT[3] = { (float)(v[1]*invW), (float)(v[2]*invW), (float)(v[3]*invW) };
    float mu[3]   = { (float)(v[4]*invW), (float)(v[5]*invW), (float)(v[6]*invW) };

    float A[3][3];
    for (int i = 0; i < 3; i++)
        for (int j = 0; j < 3; j++)
            A[i][j] = (float)(v[7 + i*3 + j] - v[1+i]*v[4+j]*invW);

    float detA = A[0][0]*(A[1][1]*A[2][2]-A[1][2]*A[2][1])
               - A[0][1]*(A[1][0]*A[2][2]-A[1][2]*A[2][0])
               + A[0][2]*(A[1][0]*A[2][1]-A[1][1]*A[2][0]);

    float C[3][3];
    for (int i = 0; i < 3; i++)
        for (int j = 0; j < 3; j++) {
            float s = 0.f;
            for (int k = 0; k < 3; k++) s += A[k][i]*A[k][j];
            C[i][j] = s;
        }
    float V[3][3] = {{1,0,0},{0,1,0},{0,0,1}};
#pragma unroll
    for (int sweep = 0; sweep < 6; sweep++) {
#pragma unroll
        for (int p = 0; p < 3; p++)
#pragma unroll
            for (int q = p+1; q < 3; q++) {
                float apq = C[p][q];
                if (apq == 0.f) continue;
                float theta = __fdividef(C[q][q] - C[p][p], 2.f * apq);
                float tt = (theta >= 0.f ? 1.f : -1.f) *
                           __fdividef(1.f, fabsf(theta) + sqrtf(theta*theta + 1.f));
                float c = rsqrtf(tt*tt + 1.f), s = tt * c;
                for (int k = 0; k < 3; k++) {
                    float a = C[k][p], bb = C[k][q];
                    C[k][p] = c*a - s*bb;  C[k][q] = s*a + c*bb;
                }
                for (int k = 0; k < 3; k++) {
                    float a = C[p][k], bb = C[q][k];
                    C[p][k] = c*a - s*bb;  C[q][k] = s*a + c*bb;
                }
                for (int k = 0; k < 3; k++) {
                    float a = V[k][p], bb = V[k][q];
                    V[k][p] = c*a - s*bb;  V[k][q] = s*a + c*bb;
                }
            }
    }
    float eig[3] = { C[0][0], C[1][1], C[2][2] };
    int idx[3] = {0, 1, 2};
    for (int i = 0; i < 2; i++)
        for (int j = i+1; j < 3; j++)
            if (eig[idx[j]] > eig[idx[i]]) { int tmp = idx[i]; idx[i] = idx[j]; idx[j] = tmp; }

    float emax = fmaxf(eig[idx[0]], 0.f);
    float dinv[3];
    for (int i = 0; i < 3; i++) {
        float e = fmaxf(eig[idx[i]], 0.f);
        dinv[i] = (e > 1e-12f * emax && e > 0.f) ? rsqrtf(e) : 0.f;
    }
    if (detA < 0.f) dinv[2] = -dinv[2];

    float T[3][3];
    for (int i = 0; i < 3; i++)
        for (int j = 0; j < 3; j++) {
            float s = 0.f;
            for (int k = 0; k < 3; k++) s += A[i][k] * V[k][idx[j]];
            T[i][j] = s * dinv[j];
        }
    for (int i = 0; i < 3; i++)
        for (int j = 0; j < 3; j++) {
            float s = 0.f;
            for (int k = 0; k < 3; k++) s += T[i][k] * V[j][idx[k]];
            g_par[b][i*3 + j] = s;
        }
    g_par[b][9]  = mu[0];   g_par[b][10] = mu[1];   g_par[b][11] = mu[2];
    g_par[b][12] = muGT[0]; g_par[b][13] = muGT[1]; g_par[b][14] = muGT[2];
    g_W[b] = W;
}

// ---------------------------------------------------------------------------
// Fallback K1 (only used when fused grid would exceed one wave).
// ---------------------------------------------------------------------------
__global__ void __launch_bounds__(256)
reduce_solve_kernel(const float* __restrict__ pred,
                    const float* __restrict__ gt,
                    const float* __restrict__ w,
                    int N, int blocksPerB)
{
    const int b   = blockIdx.x / blocksPerB;
    const int blk = blockIdx.x % blocksPerB;
    const int t   = threadIdx.x;
    const float* pb = pred + (size_t)b * N * 3;
    const float* gb = gt   + (size_t)b * N * 3;
    const float* wb = w    + (size_t)b * N;

    float acc[16];
#pragma unroll
    for (int i = 0; i < 16; i++) acc[i] = 0.f;
    for (int n = blk * blockDim.x + t; n < N; n += blocksPerB * blockDim.x) {
        float wn = wb[n];
        float px = pb[3*n], py = pb[3*n+1], pz = pb[3*n+2];
        float gx = gb[3*n], gy = gb[3*n+1], gz = gb[3*n+2];
        float wpx = wn*px, wpy = wn*py, wpz = wn*pz;
        acc[0] += wn;
        acc[1] += wpx;  acc[2] += wpy;  acc[3] += wpz;
        acc[4] += wn*gx; acc[5] += wn*gy; acc[6] += wn*gz;
        acc[7] += wpx*gx; acc[8] += wpx*gy; acc[9] += wpx*gz;
        acc[10] += wpy*gx; acc[11] += wpy*gy; acc[12] += wpy*gz;
        acc[13] += wpz*gx; acc[14] += wpz*gy; acc[15] += wpz*gz;
    }
    const unsigned mask = 0xffffffffu;
#pragma unroll
    for (int i = 0; i < 16; i++)
        for (int o = 16; o > 0; o >>= 1)
            acc[i] += __shfl_down_sync(mask, acc[i], o);
    __shared__ double sred[8][16];
    int warp = t >> 5, lane = t & 31;
    if (lane == 0)
#pragma unroll
        for (int i = 0; i < 16; i++) sred[warp][i] = (double)acc[i];
    __syncthreads();
    if (t != 0) return;
    double v[16];
#pragma unroll
    for (int i = 0; i < 16; i++) {
        double s = 0.0;
        for (int wi = 0; wi < 8; wi++) s += sred[wi][i];
        g_part[b][blk][i] = s;
    }
    __threadfence();
    unsigned old = atomicInc(&g_cnt[b], (unsigned)(blocksPerB - 1));
    if (old != (unsigned)(blocksPerB - 1)) return;
    __threadfence();
    double vv[16];
    for (int i = 0; i < 16; i++) {
        double s = 0.0;
        for (int k = 0; k < blocksPerB; k++) s += g_part[b][k][i];
        vv[i] = s;
    }
    kabsch_solve(vv, b);
    g_num1[b] = 0.0;
    if (b == 0) g_bond = 0.0;
    __threadfence();
}

// ---------------------------------------------------------------------------
// Fused kernel (512 threads): row = t & 255, j-half = t >> 8.
// ---------------------------------------------------------------------------
__global__ void __launch_bounds__(NTHR)
fused_kernel(const float* __restrict__ pred,
             const float* __restrict__ gt,
             const float* __restrict__ w,
             const float* __restrict__ ht,
             float* __restrict__ out,
             int N, int B, int tilesI, int ntri, int precomputed)
{
    const int t = threadIdx.x;
    const int row = t & (TILE - 1);
    const int jh  = t >> 8;            // 0 or 1
    const int nOff = ntri - tilesI;
    const int blk = blockIdx.x;

    int b, ti, tj;
    bool diag;
    if (blk < B * tilesI) {            // diagonal tiles first
        diag = true;
        b = blk / tilesI;
        ti = tj = blk % tilesI;
    } else {
        diag = false;
        int rem = blk - B * tilesI;
        b = rem / nOff;
        int r2 = rem % nOff;
        ti = 0;
        int rowlen = tilesI - 1;
        while (r2 >= rowlen) { r2 -= rowlen; ti++; rowlen--; }
        tj = ti + 1 + r2;
    }

    const float* pb = pred + (size_t)b * N * 3;
    const float* gb = gt   + (size_t)b * N * 3;
    const float* wb = w    + (size_t)b * N;

    __shared__ float4 sA[TILE];   // (px, gx, py, gy)
    __shared__ float4 sB[TILE];   // (pz, gz, |p|^2, |g|^2)
    __shared__ float  sW[TILE];   // w_j
    __shared__ double sred[8][16];
    __shared__ double sredp[NTHR/32];
    __shared__ double sreda[8];

    // ---- load j tile into shared (threads 0..255) ----
    if (t < TILE) {
        int j = tj * TILE + t;
        float px=0.f,py=0.f,pz=0.f,gx=0.f,gy=0.f,gz=0.f,wj=0.f;
        if (j < N) {
            px = pb[3*j]; py = pb[3*j+1]; pz = pb[3*j+2];
            gx = gb[3*j]; gy = gb[3*j+1]; gz = gb[3*j+2];
            wj = wb[j];
        }
        sA[t] = make_float4(px, gx, py, gy);
        sB[t] = make_float4(pz, gz, px*px+py*py+pz*pz, gx*gx+gy*gy+gz*gz);
        sW[t] = wj;
    }

    // ---- i-row registers ----
    int i0 = ti * TILE + row;
    float p0x=0.f,p0y=0.f,p0z=0.f,g0x=0.f,g0y=0.f,g0z=0.f,w0=0.f;
    if (i0 < N) {
        p0x = pb[3*i0]; p0y = pb[3*i0+1]; p0z = pb[3*i0+2]; w0 = wb[i0];
        g0x = gb[3*i0]; g0y = gb[3*i0+1]; g0z = gb[3*i0+2];
    }
    float pn2_0 = p0x*p0x + p0y*p0y + p0z*p0z;
    float gn2_0 = g0x*g0x + g0y*g0y + g0z*g0z;

    unsigned long long axg, ayg, azg, base;
    PACK_F32X2(axg, -2.f*p0x, -2.f*g0x);
    PACK_F32X2(ayg, -2.f*p0y, -2.f*g0y);
    PACK_F32X2(azg, -2.f*p0z, -2.f*g0z);
    PACK_F32X2(base, pn2_0, gn2_0);

    const unsigned mask = 0xffffffffu;
    int warp = t >> 5, lane = t & 31;

    // ---- stats partial (diagonal blocks, j-half 0 threads own rows) ----
    if (diag && !precomputed && jh == 0) {
        float acc[16];
        float wpx = w0*p0x, wpy = w0*p0y, wpz = w0*p0z;
        acc[0] = w0;
        acc[1] = wpx;    acc[2] = wpy;    acc[3] = wpz;
        acc[4] = w0*g0x; acc[5] = w0*g0y; acc[6] = w0*g0z;
        acc[7] = wpx*g0x; acc[8] = wpx*g0y; acc[9] = wpx*g0z;
        acc[10] = wpy*g0x; acc[11] = wpy*g0y; acc[12] = wpy*g0z;
        acc[13] = wpz*g0x; acc[14] = wpz*g0y; acc[15] = wpz*g0z;
#pragma unroll
        for (int i = 0; i < 16; i++)
            for (int o = 16; o > 0; o >>= 1)
                acc[i] += __shfl_down_sync(mask, acc[i], o);
        if (lane == 0)
#pragma unroll
            for (int i = 0; i < 16; i++) sred[warp][i] = (double)acc[i];
    }
    __syncthreads();   // covers shared tile fill AND sred writes

    if (diag && !precomputed && t == 0) {
        double v[16];
#pragma unroll
        for (int i = 0; i < 16; i++) {
            double s = 0.0;
            for (int wi = 0; wi < 8; wi++) s += sred[wi][i];
            g_part[b][ti][i] = s;
        }
        __threadfence();
        unsigned old = atomicInc(&g_cnt[b], (unsigned)(tilesI - 1));
        if (old == (unsigned)(tilesI - 1)) {
            __threadfence();
            double vv[16];
            for (int i = 0; i < 16; i++) {
                double s = 0.0;
                for (int k = 0; k < tilesI; k++) s += g_part[b][k][i];
                vv[i] = s;
            }
            kabsch_solve(vv, b);
            __threadfence();
            atomicExch(&g_ready[b], 1);
        }
    }

    // ---- bond half-tile: f32x2 packed (dp2, dg2) together ----
    float acc0 = 0.f;
    const int k0 = jh * (TILE/2);
#pragma unroll 8
    for (int kk = 0; kk < TILE/2; kk++) {
        int k = k0 + kk;
        ulonglong2 A = *reinterpret_cast<const ulonglong2*>(&sA[k]);
        ulonglong2 Bv = *reinterpret_cast<const ulonglong2*>(&sB[k]);
        float wj = sW[k];
        unsigned long long d2;
        ADD_F32X2(d2, base, Bv.y);        // (pn2_i+pn2_j, gn2_i+gn2_j)
        FMA_F32X2(d2, axg, A.x, d2);      // -2 px*pjx | -2 gx*gjx
        FMA_F32X2(d2, ayg, A.y, d2);
        FMA_F32X2(d2, azg, Bv.x, d2);
        float dp2, dg2;
        UNPACK_F32X2(dp2, dg2, d2);
        float prod = fmaxf(dp2 * dg2, 0.f);
        float s = fsqrt_approx(prod);
        float term = fmaf(-2.f, s, dp2 + dg2);
        acc0 = fmaf(wj, term, acc0);
    }
    acc0 *= w0;

    double tot = (double)acc0;
    if (!diag) tot *= 2.0;         // symmetry
    for (int o = 16; o > 0; o >>= 1)
        tot += __shfl_down_sync(mask, tot, o);
    if (lane == 0) sredp[warp] = tot;

    // ---- fused alignment loss (diagonal blocks, j-half 0) ----
    if (diag) {
        if (!precomputed && t == 0) {
            while (atomicAdd(&g_ready[b], 0) == 0) {}
            __threadfence();
        }
        __syncthreads();
        if (jh == 0) {
            float R00 = g_par[b][0], R01 = g_par[b][1], R02 = g_par[b][2];
            float R10 = g_par[b][3], R11 = g_par[b][4], R12 = g_par[b][5];
            float R20 = g_par[b][6], R21 = g_par[b][7], R22 = g_par[b][8];
            float mux = g_par[b][9],  muy = g_par[b][10], muz = g_par[b][11];
            float mgx = g_par[b][12], mgy = g_par[b][13], mgz = g_par[b][14];

            float gx = g0x - mux, gy = g0y - muy, gz = g0z - muz;
            float ax = R00*gx + R01*gy + R02*gz + mgx;
            float ay = R10*gx + R11*gy + R12*gz + mgy;
            float az = R20*gx + R21*gy + R22*gz + mgz;
            float dx = p0x - ax, dy = p0y - ay, dz = p0z - az;
            float sq = dx*dx + dy*dy + dz*dz;
            double al = (double)(w0 * fsqrt_approx(sq));
            for (int o = 16; o > 0; o >>= 1)
                al += __shfl_down_sync(mask, al, o);
            if (lane == 0) sreda[warp] = al;
        }
        __syncthreads();
        if (t == 0) {
            double s = 0.0;
            for (int wi = 0; wi < 8; wi++) s += sreda[wi];
            atomicAdd(&g_num1[b], s);
        }
    } else {
        __syncthreads();
        __syncthreads();
    }

    // ---- block totals + global completion ----
    if (t == 0) {
        double s = 0.0;
        for (int wi = 0; wi < NTHR/32; wi++) s += sredp[wi];
        atomicAdd(&g_bond, s);
        __threadfence();
        unsigned old = atomicInc(&g_done, (unsigned)(gridDim.x - 1));
        if (old == (unsigned)(gridDim.x - 1)) {
            __threadfence();
            double sw = 0.0, sw2 = 0.0, sn = 0.0;
            for (int bb = 0; bb < B; bb++) {
                double W = g_W[bb];
                sw += W; sw2 += W * W; sn += g_num1[bb];
            }
            double loss = sn / sw + g_bond / sw2;   // ALPHA_BOND = 1
            for (int bb = 0; bb < B; bb++) {
                double h = (double)ht[bb];
                out[bb] = (float)(((h*h + 256.0) / ((h + 16.0) * (h + 16.0))) * loss);
            }
            g_bond = 0.0;
            for (int bb = 0; bb < B; bb++) { g_num1[bb] = 0.0; g_ready[bb] = 0; }
            __threadfence();
        }
    }
}

extern "C" void kernel_launch(void* const* d_in, const int* in_sizes, int n_in,
                              void* d_out, int out_size)
{
    const float* pred = (const float*)d_in[0];
    const float* gt   = (const float*)d_in[1];
    const float* ht   = (const float*)d_in[2];
    const float* w    = (const float*)d_in[3];
    int B = in_sizes[2];
    int N = in_sizes[3] / B;

    int tilesI = (N + TILE - 1) / TILE;
    int ntri = tilesI * (tilesI + 1) / 2;
    int grid = B * ntri;

    if (grid <= 148 && tilesI <= MAXBLK && B <= MAXB) {
        fused_kernel<<<grid, NTHR>>>(pred, gt, w, ht, (float*)d_out,
                                     N, B, tilesI, ntri, 0);
    } else {
        int blocksPerB = (N + 255) / 256;
        if (blocksPerB > MAXBLK) blocksPerB = MAXBLK;
        reduce_solve_kernel<<<B * blocksPerB, 256>>>(pred, gt, w, N, blocksPerB);
        fused_kernel<<<grid, NTHR>>>(pred, gt, w, ht, (float*)d_out,
                                     N, B, tilesI, ntri, 1);
    }
}